// round 14
// baseline (speedup 1.0000x reference)
#include <cuda_runtime.h>
#include <math.h>
#include <stdint.h>

#define NT 365
#define NS 2048
#define NH 64
#define NG 128
#define NW 513   // NH*8+1

#define GEMM_BLOCKS 1024                      // 64 site-tiles x 16 j-tiles
#define PART_BLOCKS ((NT * NS + 255) / 256)   // 2920

// ---------------- scratch (static device globals; no allocation) -------------
__device__ float4 g_flux[(NT + 8) * NS];   // [t][s] = {ps, pl, e, relu(Ta)}
__device__ float  g_w[(size_t)NS * 512];   // fc output w[s][j], j in [0,512)

__device__ __forceinline__ float sigmoidf_(float x) {
    return 1.0f / (1.0f + expf(-x));
}

// ---------------- kernel A: fused rain/snow partition + GEMM ------------------
__global__ void __launch_bounds__(256) k_pre(const float4* __restrict__ x,
                                             const float* __restrict__ xc,
                                             const float* __restrict__ W,
                                             const float* __restrict__ b) {
    __shared__ float xs[32 * 132];   // [site][c], padded stride
    __shared__ float ws[32 * 128];   // [j_local][c]
    int tid = threadIdx.x;

    if (blockIdx.x < GEMM_BLOCKS) {
        int s0 = (blockIdx.x & 63) << 5;      // 64 site-tiles
        int jbase = (blockIdx.x >> 6) << 5;   // 16 j-tiles

        for (int idx = tid; idx < 32 * NG; idx += 256) {
            int sl = idx >> 7, c = idx & (NG - 1);
            xs[sl * 132 + c] = xc[(size_t)(s0 + sl) * NG + c];
        }
        {
            const float4* Wt = (const float4*)(W + (size_t)jbase * NG);
            float4* ws4 = (float4*)ws;
            for (int idx = tid; idx < 32 * NG / 4; idx += 256)
                ws4[idx] = Wt[idx];
        }
        __syncthreads();

        int sl = tid & 31;
        int joff = tid >> 5;
        float acc[4] = {0.f, 0.f, 0.f, 0.f};
        const float4* xv4 = (const float4*)&xs[sl * 132];
        const float4* wr0 = (const float4*)&ws[(joff +  0) * NG];
        const float4* wr1 = (const float4*)&ws[(joff +  8) * NG];
        const float4* wr2 = (const float4*)&ws[(joff + 16) * NG];
        const float4* wr3 = (const float4*)&ws[(joff + 24) * NG];

#pragma unroll 8
        for (int c4 = 0; c4 < NG / 4; ++c4) {
            float4 xv = xv4[c4];
            float4 w0 = wr0[c4], w1 = wr1[c4], w2 = wr2[c4], w3 = wr3[c4];
            acc[0] += xv.x * w0.x + xv.y * w0.y + xv.z * w0.z + xv.w * w0.w;
            acc[1] += xv.x * w1.x + xv.y * w1.y + xv.z * w1.z + xv.w * w1.w;
            acc[2] += xv.x * w2.x + xv.y * w2.y + xv.z * w2.z + xv.w * w2.w;
            acc[3] += xv.x * w3.x + xv.y * w3.y + xv.z * w3.z + xv.w * w3.w;
        }
#pragma unroll
        for (int i = 0; i < 4; i++) {
            int j = jbase + joff + i * 8;
            g_w[(size_t)(s0 + sl) * 512 + j] = acc[i] + b[j];
        }
    } else {
        int i = (blockIdx.x - GEMM_BLOCKS) * 256 + tid;
        if (i >= NT * NS) return;
        float4 v = x[i];
        float P = v.x, E = v.y, T1 = v.z, T2 = v.w;
        float Ta = 0.5f * (T1 + T2);
        float rP;
        if (T1 >= 0.0f)      rP = 1.0f;
        else if (T2 <= 0.0f) rP = 0.0f;
        else                 rP = 1.0f - acosf((T1 + T2) / (T2 - T1)) / 3.1415f;
        float pl = rP * P;
        float ps = (1.0f - rP) * P;
        g_flux[i] = make_float4(ps, pl, E, fmaxf(Ta, 0.0f));
    }
}

// ---------------- kernel B: fused params + sequential scan --------------------
// 2 warps per site (4096 warps, 2048 blocks x 64 thr). Warp q owns
// h = q*32 + lane, ONE scalar chain per lane. Params computed in the prologue
// per warp (cross-warp softmax via smem). Per-warp select-transpose reduction,
// pipelined over the 4-step unroll; half-site partials combine via
// double-buffered smem + one __syncthreads per block.
__global__ void __launch_bounds__(64) k_scan(float* __restrict__ out,
                                             const float* __restrict__ xc,
                                             const float* __restrict__ W,
                                             const float* __restrict__ b) {
    int lane = threadIdx.x & 31;
    int q    = threadIdx.x >> 5;   // half: 0 or 1
    int l3   = lane & 3;
    int s    = blockIdx.x;
    int h    = q * 32 + lane;

    __shared__ float sred[4];      // [0..1]=max, [2..3]=sum
    __shared__ float sbuf[2][4];   // double-buffered half-site partials

    // ================= prologue: params in registers =================
    const float* wr = g_w + (size_t)s * 512;
    float wgm = wr[0 * NH + h];
    float wge = wr[1 * NH + h];
    float wk0 = wr[3 * NH + h];
    float wk1 = wr[4 * NH + h];
    float wk2 = wr[5 * NH + h];
    float wgl = wr[6 * NH + h];
    float wkb = wr[7 * NH + h];

    // w512 = xc[s]·W[512] + b[512]  (both warps redundantly)
    float p = 0.f;
    const float* w512row = W + 512 * NG;
    const float* xcr = xc + (size_t)s * NG;
#pragma unroll
    for (int k = 0; k < 4; k++)
        p = fmaf(xcr[lane + 32 * k], w512row[lane + 32 * k], p);
#pragma unroll
    for (int o = 16; o; o >>= 1) p += __shfl_xor_sync(0xffffffffu, p, o);
    float w512 = p + b[512];
    float vi = sigmoidf_(w512);
    float qb = fmaxf(w512, 0.f) / (float)NH;

    // softmax over the 64 k1 pre-activations (across both warps)
    float mx = wk1;
#pragma unroll
    for (int o = 16; o; o >>= 1) mx = fmaxf(mx, __shfl_xor_sync(0xffffffffu, mx, o));
    if (lane == 0) sred[q] = mx;
    __syncthreads();
    mx = fmaxf(sred[0], sred[1]);
    float e1 = expf(wk1 - mx);
    float sum = e1;
#pragma unroll
    for (int o = 16; o; o >>= 1) sum += __shfl_xor_sync(0xffffffffu, sum, o);
    if (lane == 0) sred[2 + q] = sum;
    __syncthreads();
    float ga = e1 / (sred[2] + sred[3]);

    float k0 = sigmoidf_(wk0);
    float k1 = sigmoidf_(wk1);
    float k2 = sigmoidf_(wk2);
    float kb = sigmoidf_(wkb) / 10.0f;
    float kkb = k1 * kb;

    float gm   = expf(wgm) + 1.0f;
    float nge  = -2.0f * sigmoidf_(wge);
    float gl   = expf(wgl);
    float ngl  = -gl;
    float k0m  = 1.0f - k0;
    float k0ga = k0 * ga;
    float nk1  = -k1;
    float k2m  = 1.0f - k2;
    float k2ga = k2 * ga;
    float kd   = kkb * k2m;
    float kq1c = k1 * (1.0f - kb) * ga + kkb * k2ga;

    // ================= main loop =================
    float S0 = 0.f, H0 = ngl, H1 = 0.f, H2 = 0.f;
    float yv[4], ry[4], rv;

#define STEP(F, K)                                                             \
    {                                                                          \
        float ps = F.x, pl = F.y, e = F.z, tap = F.w;                          \
        float plvi = pl * vi;                                                  \
        float plv1 = pl - plvi;                                                \
        float am = tap * gm;                                                   \
        float Sm = fminf(S0, am);                                              \
        S0 = (S0 - Sm) + ps;                                                   \
        float G1 = fmaxf((H1 + Sm) + fmaf(e, nge, plvi), 0.f);                 \
        float G0 = fmaxf((H0 + G1) + plv1, 0.f);                               \
        H0 = fmaf(G0, k0m, ngl);                                               \
        float y = G0 * k0ga;                                                   \
        float m1 = fminf(G1, gl);                                              \
        H1 = fminf(fmaf(m1, nk1, G1), gl);                                     \
        y = fmaf(H2, k2ga, y);                                                 \
        y = fmaf(m1, kq1c, y);                                                 \
        float h2t = H2 * k2m;                                                  \
        H2 = fmaf(m1, kd, h2t);                                                \
        yv[K] = y;                                                             \
    }

#define RSTAGE4(o)                                                             \
    {                                                                          \
        float u0 = __shfl_xor_sync(0xffffffffu, ry[0], (o));                   \
        float u1 = __shfl_xor_sync(0xffffffffu, ry[1], (o));                   \
        float u2 = __shfl_xor_sync(0xffffffffu, ry[2], (o));                   \
        float u3 = __shfl_xor_sync(0xffffffffu, ry[3], (o));                   \
        ry[0] += u0; ry[1] += u1; ry[2] += u2; ry[3] += u3;                    \
    }
#define RSEL()                                                                 \
    {                                                                          \
        float rw;                                                              \
        rv = (l3 & 1) ? ry[1] : ry[0];                                         \
        rw = (l3 & 1) ? ry[3] : ry[2];                                         \
        rv = (l3 & 2) ? rw : rv;                                               \
    }
#define RSTAGE1(o) rv += __shfl_xor_sync(0xffffffffu, rv, (o));

    // combine half-site partials: double-buffered smem + one barrier per block
#define RCOMBINE(T, B)                                                         \
    {                                                                          \
        if (q && lane < 4) sbuf[B][lane] = rv;                                 \
        __syncthreads();                                                       \
        if (!q && lane < 4)                                                    \
            out[(size_t)((T) + lane) * NS + s] = (rv + sbuf[B][lane]) + qb;    \
    }

    // preload flux for block 0 (t = 0..3)
    float4 fc0 = g_flux[0 * NS + s];
    float4 fc1 = g_flux[1 * NS + s];
    float4 fc2 = g_flux[2 * NS + s];
    float4 fc3 = g_flux[3 * NS + s];

    // block 0: compute only (its reduction happens inside iteration tb=1)
    {
        float4 fn0 = g_flux[(size_t)4 * NS + s];
        float4 fn1 = g_flux[(size_t)5 * NS + s];
        float4 fn2 = g_flux[(size_t)6 * NS + s];
        float4 fn3 = g_flux[(size_t)7 * NS + s];
        STEP(fc0, 0)
        STEP(fc1, 1)
        STEP(fc2, 2)
        STEP(fc3, 3)
        ry[0] = yv[0]; ry[1] = yv[1]; ry[2] = yv[2]; ry[3] = yv[3];
        fc0 = fn0; fc1 = fn1; fc2 = fn2; fc3 = fn3;
    }

    // main loop: blocks 1..90 (t = 4..363), reduce block tb-1 interleaved
    for (int tb = 1; tb < 91; ++tb) {
        int t = tb * 4;
        float4 fn0 = g_flux[(size_t)(t + 4) * NS + s];
        float4 fn1 = g_flux[(size_t)(t + 5) * NS + s];
        float4 fn2 = g_flux[(size_t)(t + 6) * NS + s];
        float4 fn3 = g_flux[(size_t)(t + 7) * NS + s];

        STEP(fc0, 0)
        RSTAGE4(1)
        STEP(fc1, 1)
        RSTAGE4(2)
        STEP(fc2, 2)
        RSEL()
        RSTAGE1(4)
        STEP(fc3, 3)
        RSTAGE1(8)
        RSTAGE1(16)
        RCOMBINE(t - 4, (tb - 1) & 1)

        ry[0] = yv[0]; ry[1] = yv[1]; ry[2] = yv[2]; ry[3] = yv[3];
        fc0 = fn0; fc1 = fn1; fc2 = fn2; fc3 = fn3;
    }

    // drain block 90 reduction (t = 360..363)
    RSTAGE4(1) RSTAGE4(2) RSEL() RSTAGE1(4) RSTAGE1(8) RSTAGE1(16)
    RCOMBINE(360, 0)

    // epilogue: t = 364 (fc0 holds flux row 364 after last rotate)
    STEP(fc0, 0)
    rv = yv[0];
#pragma unroll
    for (int o = 16; o; o >>= 1) rv += __shfl_xor_sync(0xffffffffu, rv, o);
    {
        if (q && lane == 0) sbuf[1][0] = rv;
        __syncthreads();
        if (!q && lane == 0) out[(size_t)364 * NS + s] = (rv + sbuf[1][0]) + qb;
    }
#undef STEP
#undef RSTAGE4
#undef RSEL
#undef RSTAGE1
#undef RCOMBINE
}

// ---------------- launch ------------------------------------------------------
extern "C" void kernel_launch(void* const* d_in, const int* in_sizes, int n_in,
                              void* d_out, int out_size) {
    const float* x  = (const float*)d_in[0];  // [NT, NS, 4]
    const float* xc = (const float*)d_in[1];  // [NS, NG]
    const float* W  = (const float*)d_in[2];  // [NW, NG]
    const float* b  = (const float*)d_in[3];  // [NW]
    float* out = (float*)d_out;               // [NT, NS]

    k_pre<<<GEMM_BLOCKS + PART_BLOCKS, 256>>>((const float4*)x, xc, W, b);
    k_scan<<<NS, 64>>>(out, xc, W, b);   // 2048 blocks; 2 warps per site
}

// round 15
// speedup vs baseline: 1.2233x; 1.2233x over previous
#include <cuda_runtime.h>
#include <math.h>
#include <stdint.h>

#define NT 365
#define NS 2048
#define NH 64
#define NG 128
#define NW 513   // NH*8+1

#define GEMM_BLOCKS 1024                      // 64 site-tiles x 16 j-tiles
#define PART_BLOCKS ((NT * NS + 255) / 256)   // 2920

// ---------------- scratch (static device globals; no allocation) -------------
__device__ float4 g_flux[(NT + 16) * NS];  // [t][s] = {ps, pl, e, relu(Ta)}; padded
__device__ float  g_w[(size_t)NS * 512];   // fc output w[s][j], j in [0,512)

__device__ __forceinline__ float sigmoidf_(float x) {
    return 1.0f / (1.0f + expf(-x));
}

// ---------------- kernel A: fused rain/snow partition + GEMM ------------------
__global__ void __launch_bounds__(256) k_pre(const float4* __restrict__ x,
                                             const float* __restrict__ xc,
                                             const float* __restrict__ W,
                                             const float* __restrict__ b) {
    __shared__ float xs[32 * 132];   // [site][c], padded stride
    __shared__ float ws[32 * 128];   // [j_local][c]
    int tid = threadIdx.x;

    if (blockIdx.x < GEMM_BLOCKS) {
        int s0 = (blockIdx.x & 63) << 5;      // 64 site-tiles
        int jbase = (blockIdx.x >> 6) << 5;   // 16 j-tiles

        for (int idx = tid; idx < 32 * NG; idx += 256) {
            int sl = idx >> 7, c = idx & (NG - 1);
            xs[sl * 132 + c] = xc[(size_t)(s0 + sl) * NG + c];
        }
        {
            const float4* Wt = (const float4*)(W + (size_t)jbase * NG);
            float4* ws4 = (float4*)ws;
            for (int idx = tid; idx < 32 * NG / 4; idx += 256)
                ws4[idx] = Wt[idx];
        }
        __syncthreads();

        int sl = tid & 31;
        int joff = tid >> 5;
        float acc[4] = {0.f, 0.f, 0.f, 0.f};
        const float4* xv4 = (const float4*)&xs[sl * 132];
        const float4* wr0 = (const float4*)&ws[(joff +  0) * NG];
        const float4* wr1 = (const float4*)&ws[(joff +  8) * NG];
        const float4* wr2 = (const float4*)&ws[(joff + 16) * NG];
        const float4* wr3 = (const float4*)&ws[(joff + 24) * NG];

#pragma unroll 8
        for (int c4 = 0; c4 < NG / 4; ++c4) {
            float4 xv = xv4[c4];
            float4 w0 = wr0[c4], w1 = wr1[c4], w2 = wr2[c4], w3 = wr3[c4];
            acc[0] += xv.x * w0.x + xv.y * w0.y + xv.z * w0.z + xv.w * w0.w;
            acc[1] += xv.x * w1.x + xv.y * w1.y + xv.z * w1.z + xv.w * w1.w;
            acc[2] += xv.x * w2.x + xv.y * w2.y + xv.z * w2.z + xv.w * w2.w;
            acc[3] += xv.x * w3.x + xv.y * w3.y + xv.z * w3.z + xv.w * w3.w;
        }
#pragma unroll
        for (int i = 0; i < 4; i++) {
            int j = jbase + joff + i * 8;
            g_w[(size_t)(s0 + sl) * 512 + j] = acc[i] + b[j];
        }
    } else {
        int i = (blockIdx.x - GEMM_BLOCKS) * 256 + tid;
        if (i >= NT * NS) return;
        float4 v = x[i];
        float P = v.x, E = v.y, T1 = v.z, T2 = v.w;
        float Ta = 0.5f * (T1 + T2);
        float rP;
        if (T1 >= 0.0f)      rP = 1.0f;
        else if (T2 <= 0.0f) rP = 0.0f;
        else                 rP = 1.0f - acosf((T1 + T2) / (T2 - T1)) / 3.1415f;
        float pl = rP * P;
        float ps = (1.0f - rP) * P;
        g_flux[i] = make_float4(ps, pl, E, fmaxf(Ta, 0.0f));
    }
}

// ---------------- kernel B: fused params + sequential scan --------------------
// 1 warp per site (2048 warps). Prologue: folded params in registers.
// Main loop unrolled x8; each lane carries two independent scalar chains
// (h = lane, h = lane+32). Reduction of block i (8 timesteps) is software-
// pipelined into block i+1 via 8-wide select-transpose; lanes 0..3 store.
__global__ void __launch_bounds__(64) k_scan(float* __restrict__ out,
                                             const float* __restrict__ xc,
                                             const float* __restrict__ W,
                                             const float* __restrict__ b) {
    int lane = threadIdx.x & 31;
    int l3 = lane & 3;
    int s = blockIdx.x * 2 + (threadIdx.x >> 5);

    // ================= prologue: params in registers =================
    const float* wr = g_w + (size_t)s * 512;
    int hA = lane, hB = lane + 32;
    float wgmA = wr[0 * NH + hA], wgmB = wr[0 * NH + hB];
    float wgeA = wr[1 * NH + hA], wgeB = wr[1 * NH + hB];
    float wk0A = wr[3 * NH + hA], wk0B = wr[3 * NH + hB];
    float wk1A = wr[4 * NH + hA], wk1B = wr[4 * NH + hB];
    float wk2A = wr[5 * NH + hA], wk2B = wr[5 * NH + hB];
    float wglA = wr[6 * NH + hA], wglB = wr[6 * NH + hB];
    float wkbA = wr[7 * NH + hA], wkbB = wr[7 * NH + hB];

    // w512 = xc[s]·W[512] + b[512]
    float p = 0.f;
    const float* w512row = W + 512 * NG;
    const float* xcr = xc + (size_t)s * NG;
#pragma unroll
    for (int k = 0; k < 4; k++)
        p = fmaf(xcr[lane + 32 * k], w512row[lane + 32 * k], p);
#pragma unroll
    for (int o = 16; o; o >>= 1) p += __shfl_xor_sync(0xffffffffu, p, o);
    float w512 = p + b[512];
    float vi = sigmoidf_(w512);
    float qb = fmaxf(w512, 0.f) / (float)NH;

    // softmax over the k1 pre-activation slice (64 values across the warp)
    float mx = fmaxf(wk1A, wk1B);
#pragma unroll
    for (int o = 16; o; o >>= 1) mx = fmaxf(mx, __shfl_xor_sync(0xffffffffu, mx, o));
    float eA = expf(wk1A - mx), eB = expf(wk1B - mx);
    float sum = eA + eB;
#pragma unroll
    for (int o = 16; o; o >>= 1) sum += __shfl_xor_sync(0xffffffffu, sum, o);
    float inv = 1.0f / sum;
    float gaA = eA * inv, gaB = eB * inv;

    float k0A = sigmoidf_(wk0A),          k0B = sigmoidf_(wk0B);
    float k1A = sigmoidf_(wk1A),          k1B = sigmoidf_(wk1B);
    float k2A = sigmoidf_(wk2A),          k2B = sigmoidf_(wk2B);
    float kbA = sigmoidf_(wkbA) / 10.0f,  kbB = sigmoidf_(wkbB) / 10.0f;
    float kkbA = k1A * kbA,               kkbB = k1B * kbB;

    float2 gm    = make_float2(expf(wgmA) + 1.0f,       expf(wgmB) + 1.0f);
    float2 nge   = make_float2(-2.0f * sigmoidf_(wgeA), -2.0f * sigmoidf_(wgeB));
    float2 gl    = make_float2(expf(wglA),              expf(wglB));
    float2 ngl   = make_float2(-gl.x,                   -gl.y);
    float2 k0m   = make_float2(1.0f - k0A,              1.0f - k0B);
    float2 k0ga  = make_float2(k0A * gaA,               k0B * gaB);
    float2 nk1   = make_float2(-k1A,                    -k1B);
    float2 k2m   = make_float2(1.0f - k2A,              1.0f - k2B);
    float2 k2ga  = make_float2(k2A * gaA,               k2B * gaB);
    float2 kd    = make_float2(kkbA * k2m.x,            kkbB * k2m.y);
    float2 kq1c  = make_float2(k1A * (1.0f - kbA) * gaA + kkbA * k2ga.x,
                               k1B * (1.0f - kbB) * gaB + kkbB * k2ga.y);

    // ================= main loop =================
    float S0A = 0.f, H0A = ngl.x, H1A = 0.f, H2A = 0.f;
    float S0B = 0.f, H0B = ngl.y, H1B = 0.f, H2B = 0.f;
    float yv[8], ry[8], rv, rw;

#define STEP(F, K)                                                             \
    {                                                                          \
        float ps = F.x, pl = F.y, e = F.z, tap = F.w;                          \
        float plvi = pl * vi;                                                  \
        float plv1 = pl - plvi;                                                \
        float amA = tap * gm.x;                                                \
        float SmA = fminf(S0A, amA);                                           \
        S0A = (S0A - SmA) + ps;                                                \
        float G1A = fmaxf((H1A + SmA) + fmaf(e, nge.x, plvi), 0.f);            \
        float G0A = fmaxf((H0A + G1A) + plv1, 0.f);                            \
        H0A = fmaf(G0A, k0m.x, ngl.x);                                         \
        float yA = G0A * k0ga.x;                                               \
        float m1A = fminf(G1A, gl.x);                                          \
        H1A = fminf(fmaf(m1A, nk1.x, G1A), gl.x);                              \
        yA = fmaf(H2A, k2ga.x, yA);                                            \
        yA = fmaf(m1A, kq1c.x, yA);                                            \
        float h2tA = H2A * k2m.x;                                              \
        H2A = fmaf(m1A, kd.x, h2tA);                                           \
        float amB = tap * gm.y;                                                \
        float SmB = fminf(S0B, amB);                                           \
        S0B = (S0B - SmB) + ps;                                                \
        float G1B = fmaxf((H1B + SmB) + fmaf(e, nge.y, plvi), 0.f);            \
        float G0B = fmaxf((H0B + G1B) + plv1, 0.f);                            \
        H0B = fmaf(G0B, k0m.y, ngl.y);                                         \
        float yB = G0B * k0ga.y;                                               \
        float m1B = fminf(G1B, gl.y);                                          \
        H1B = fminf(fmaf(m1B, nk1.y, G1B), gl.y);                              \
        yB = fmaf(H2B, k2ga.y, yB);                                            \
        yB = fmaf(m1B, kq1c.y, yB);                                            \
        float h2tB = H2B * k2m.y;                                              \
        H2B = fmaf(m1B, kd.y, h2tB);                                           \
        yv[K] = yA + yB;                                                       \
    }

    // butterfly stage (offset o) over deferred values [I0, I0+3]
#define RSTG(o, I0)                                                            \
    {                                                                          \
        float u0 = __shfl_xor_sync(0xffffffffu, ry[(I0) + 0], (o));            \
        float u1 = __shfl_xor_sync(0xffffffffu, ry[(I0) + 1], (o));            \
        float u2 = __shfl_xor_sync(0xffffffffu, ry[(I0) + 2], (o));            \
        float u3 = __shfl_xor_sync(0xffffffffu, ry[(I0) + 3], (o));            \
        ry[(I0) + 0] += u0; ry[(I0) + 1] += u1;                                \
        ry[(I0) + 2] += u2; ry[(I0) + 3] += u3;                                \
    }
    // select value l3 from ry[0..3] into rv, value l3+4 from ry[4..7] into rw
#define RSEL8()                                                                \
    {                                                                          \
        float a0 = (l3 & 1) ? ry[1] : ry[0];                                   \
        float a1 = (l3 & 1) ? ry[3] : ry[2];                                   \
        rv = (l3 & 2) ? a1 : a0;                                               \
        float b0 = (l3 & 1) ? ry[5] : ry[4];                                   \
        float b1 = (l3 & 1) ? ry[7] : ry[6];                                   \
        rw = (l3 & 2) ? b1 : b0;                                               \
    }
#define RSTG2(o)                                                               \
    {                                                                          \
        float u = __shfl_xor_sync(0xffffffffu, rv, (o));                       \
        float v = __shfl_xor_sync(0xffffffffu, rw, (o));                       \
        rv += u; rw += v;                                                      \
    }
#define RSTORE8(T)                                                             \
    if (lane < 4) {                                                            \
        out[(size_t)((T) + lane) * NS + s] = rv + qb;                          \
        out[(size_t)((T) + 4 + lane) * NS + s] = rw + qb;                      \
    }

#define LOAD8(T, N)                                                            \
    float4 N##0 = g_flux[(size_t)((T) + 0) * NS + s];                          \
    float4 N##1 = g_flux[(size_t)((T) + 1) * NS + s];                          \
    float4 N##2 = g_flux[(size_t)((T) + 2) * NS + s];                          \
    float4 N##3 = g_flux[(size_t)((T) + 3) * NS + s];                          \
    float4 N##4 = g_flux[(size_t)((T) + 4) * NS + s];                          \
    float4 N##5 = g_flux[(size_t)((T) + 5) * NS + s];                          \
    float4 N##6 = g_flux[(size_t)((T) + 6) * NS + s];                          \
    float4 N##7 = g_flux[(size_t)((T) + 7) * NS + s];

#define ROT8()                                                                 \
    fc0 = fn0; fc1 = fn1; fc2 = fn2; fc3 = fn3;                                \
    fc4 = fn4; fc5 = fn5; fc6 = fn6; fc7 = fn7;

    // preload flux for block 0 (t = 0..7)
    LOAD8(0, fc)

    // block 0: compute only (its reduction happens inside iteration tb=1)
    {
        LOAD8(8, fn)
        STEP(fc0, 0) STEP(fc1, 1) STEP(fc2, 2) STEP(fc3, 3)
        STEP(fc4, 4) STEP(fc5, 5) STEP(fc6, 6) STEP(fc7, 7)
#pragma unroll
        for (int k = 0; k < 8; k++) ry[k] = yv[k];
        ROT8()
    }

    // main loop: blocks 1..44 (t = 8..359), reduce block tb-1 interleaved
    for (int tb = 1; tb < 45; ++tb) {
        int t = tb * 8;
        LOAD8(t + 8, fn)

        STEP(fc0, 0)
        RSTG(1, 0)
        STEP(fc1, 1)
        RSTG(1, 4)
        STEP(fc2, 2)
        RSTG(2, 0)
        STEP(fc3, 3)
        RSTG(2, 4)
        STEP(fc4, 4)
        RSEL8()
        STEP(fc5, 5)
        RSTG2(4)
        STEP(fc6, 6)
        RSTG2(8)
        STEP(fc7, 7)
        RSTG2(16)
        RSTORE8(t - 8)

#pragma unroll
        for (int k = 0; k < 8; k++) ry[k] = yv[k];
        ROT8()
    }

    // drain block 44 reduction (t = 352..359)
    RSTG(1, 0) RSTG(1, 4) RSTG(2, 0) RSTG(2, 4)
    RSEL8() RSTG2(4) RSTG2(8) RSTG2(16)
    RSTORE8(352)

    // epilogue: t = 360..364 (fc0..fc4 hold rows 360..364 after last rotate)
    {
        float4 ep[5] = {fc0, fc1, fc2, fc3, fc4};
#pragma unroll
        for (int k = 0; k < 5; k++) {
            STEP(ep[k], 0)
            float r = yv[0];
#pragma unroll
            for (int o = 16; o; o >>= 1) r += __shfl_xor_sync(0xffffffffu, r, o);
            if (lane == 0) out[(size_t)(360 + k) * NS + s] = r + qb;
        }
    }
#undef STEP
#undef RSTG
#undef RSEL8
#undef RSTG2
#undef RSTORE8
#undef LOAD8
#undef ROT8
}

// ---------------- launch ------------------------------------------------------
extern "C" void kernel_launch(void* const* d_in, const int* in_sizes, int n_in,
                              void* d_out, int out_size) {
    const float* x  = (const float*)d_in[0];  // [NT, NS, 4]
    const float* xc = (const float*)d_in[1];  // [NS, NG]
    const float* W  = (const float*)d_in[2];  // [NW, NG]
    const float* b  = (const float*)d_in[3];  // [NW]
    float* out = (float*)d_out;               // [NT, NS]

    k_pre<<<GEMM_BLOCKS + PART_BLOCKS, 256>>>((const float4*)x, xc, W, b);
    k_scan<<<NS / 2, 64>>>(out, xc, W, b);   // fused params + scan
}

// round 16
// speedup vs baseline: 1.2494x; 1.0214x over previous
#include <cuda_runtime.h>
#include <math.h>
#include <stdint.h>

#define NT 365
#define NS 2048
#define NH 64
#define NG 128
#define NW 513   // NH*8+1

#define GEMM_BLOCKS 896                       // 64 site-tiles x 14 used j-tiles
#define PART_BLOCKS ((NT * NS + 255) / 256)   // 2920

// ---------------- scratch (static device globals; no allocation) -------------
__device__ float4 g_flux[(NT + 16) * NS];  // [t][s] = {ps, pl, e, relu(Ta)}; padded
__device__ float  g_w[(size_t)NS * 512];   // fc output w[s][j] (slice j=128..191 unused)

__device__ __forceinline__ float sigmoidf_(float x) {
    return 1.0f / (1.0f + expf(-x));
}

// ---------------- kernel A: fused rain/snow partition + GEMM ------------------
__global__ void __launch_bounds__(256) k_pre(const float4* __restrict__ x,
                                             const float* __restrict__ xc,
                                             const float* __restrict__ W,
                                             const float* __restrict__ b) {
    __shared__ float xs[32 * 132];   // [site][c], padded stride
    __shared__ float ws[32 * 128];   // [j_local][c]
    int tid = threadIdx.x;

    if (blockIdx.x < GEMM_BLOCKS) {
        int s0 = (blockIdx.x & 63) << 5;      // 64 site-tiles
        int jt = blockIdx.x >> 6;             // 0..13 used j-tiles
        int jbase = (jt << 5) + (jt >= 4 ? 64 : 0);  // skip j=128..191

        for (int idx = tid; idx < 32 * NG; idx += 256) {
            int sl = idx >> 7, c = idx & (NG - 1);
            xs[sl * 132 + c] = xc[(size_t)(s0 + sl) * NG + c];
        }
        {
            const float4* Wt = (const float4*)(W + (size_t)jbase * NG);
            float4* ws4 = (float4*)ws;
            for (int idx = tid; idx < 32 * NG / 4; idx += 256)
                ws4[idx] = Wt[idx];
        }
        __syncthreads();

        int sl = tid & 31;
        int joff = tid >> 5;
        float acc[4] = {0.f, 0.f, 0.f, 0.f};
        const float4* xv4 = (const float4*)&xs[sl * 132];
        const float4* wr0 = (const float4*)&ws[(joff +  0) * NG];
        const float4* wr1 = (const float4*)&ws[(joff +  8) * NG];
        const float4* wr2 = (const float4*)&ws[(joff + 16) * NG];
        const float4* wr3 = (const float4*)&ws[(joff + 24) * NG];

#pragma unroll 8
        for (int c4 = 0; c4 < NG / 4; ++c4) {
            float4 xv = xv4[c4];
            float4 w0 = wr0[c4], w1 = wr1[c4], w2 = wr2[c4], w3 = wr3[c4];
            acc[0] += xv.x * w0.x + xv.y * w0.y + xv.z * w0.z + xv.w * w0.w;
            acc[1] += xv.x * w1.x + xv.y * w1.y + xv.z * w1.z + xv.w * w1.w;
            acc[2] += xv.x * w2.x + xv.y * w2.y + xv.z * w2.z + xv.w * w2.w;
            acc[3] += xv.x * w3.x + xv.y * w3.y + xv.z * w3.z + xv.w * w3.w;
        }
#pragma unroll
        for (int i = 0; i < 4; i++) {
            int j = jbase + joff + i * 8;
            g_w[(size_t)(s0 + sl) * 512 + j] = acc[i] + b[j];
        }
    } else {
        int i = (blockIdx.x - GEMM_BLOCKS) * 256 + tid;
        if (i >= NT * NS) return;
        float4 v = x[i];
        float P = v.x, E = v.y, T1 = v.z, T2 = v.w;
        float Ta = 0.5f * (T1 + T2);
        float rP;
        if (T1 >= 0.0f)      rP = 1.0f;
        else if (T2 <= 0.0f) rP = 0.0f;
        else                 rP = 1.0f - acosf(__fdividef(T1 + T2, T2 - T1)) / 3.1415f;
        float pl = rP * P;
        float ps = (1.0f - rP) * P;
        g_flux[i] = make_float4(ps, pl, E, fmaxf(Ta, 0.0f));
    }
}

// ---------------- kernel B: fused params + sequential scan --------------------
// 1 warp per site (2048 warps). Main loop: 16-step ping-pong (fA/fB, yA/yB);
// each lane carries two independent scalar chains (h = lane, h = lane+32).
// Reduction of block i is software-pipelined into block i+1 via 8-wide
// select-transpose; lanes 0..3 store 8 timesteps.
__global__ void __launch_bounds__(64) k_scan(float* __restrict__ out,
                                             const float* __restrict__ xc,
                                             const float* __restrict__ W,
                                             const float* __restrict__ b) {
    int lane = threadIdx.x & 31;
    int l3 = lane & 3;
    int s = blockIdx.x * 2 + (threadIdx.x >> 5);

    // ================= prologue: params in registers =================
    const float* wr = g_w + (size_t)s * 512;
    int hA = lane, hB = lane + 32;
    float wgmA = wr[0 * NH + hA], wgmB = wr[0 * NH + hB];
    float wgeA = wr[1 * NH + hA], wgeB = wr[1 * NH + hB];
    float wk0A = wr[3 * NH + hA], wk0B = wr[3 * NH + hB];
    float wk1A = wr[4 * NH + hA], wk1B = wr[4 * NH + hB];
    float wk2A = wr[5 * NH + hA], wk2B = wr[5 * NH + hB];
    float wglA = wr[6 * NH + hA], wglB = wr[6 * NH + hB];
    float wkbA = wr[7 * NH + hA], wkbB = wr[7 * NH + hB];

    // w512 = xc[s]·W[512] + b[512]
    float p = 0.f;
    const float* w512row = W + 512 * NG;
    const float* xcr = xc + (size_t)s * NG;
#pragma unroll
    for (int k = 0; k < 4; k++)
        p = fmaf(xcr[lane + 32 * k], w512row[lane + 32 * k], p);
#pragma unroll
    for (int o = 16; o; o >>= 1) p += __shfl_xor_sync(0xffffffffu, p, o);
    float w512 = p + b[512];
    float vi = sigmoidf_(w512);
    float qb = fmaxf(w512, 0.f) / (float)NH;

    // softmax over the k1 pre-activation slice (64 values across the warp)
    float mx = fmaxf(wk1A, wk1B);
#pragma unroll
    for (int o = 16; o; o >>= 1) mx = fmaxf(mx, __shfl_xor_sync(0xffffffffu, mx, o));
    float eA = expf(wk1A - mx), eB = expf(wk1B - mx);
    float sum = eA + eB;
#pragma unroll
    for (int o = 16; o; o >>= 1) sum += __shfl_xor_sync(0xffffffffu, sum, o);
    float inv = 1.0f / sum;
    float gaA = eA * inv, gaB = eB * inv;

    float k0A = sigmoidf_(wk0A),          k0B = sigmoidf_(wk0B);
    float k1A = sigmoidf_(wk1A),          k1B = sigmoidf_(wk1B);
    float k2A = sigmoidf_(wk2A),          k2B = sigmoidf_(wk2B);
    float kbA = sigmoidf_(wkbA) / 10.0f,  kbB = sigmoidf_(wkbB) / 10.0f;
    float kkbA = k1A * kbA,               kkbB = k1B * kbB;

    float2 gm    = make_float2(expf(wgmA) + 1.0f,       expf(wgmB) + 1.0f);
    float2 nge   = make_float2(-2.0f * sigmoidf_(wgeA), -2.0f * sigmoidf_(wgeB));
    float2 gl    = make_float2(expf(wglA),              expf(wglB));
    float2 ngl   = make_float2(-gl.x,                   -gl.y);
    float2 k0m   = make_float2(1.0f - k0A,              1.0f - k0B);
    float2 k0ga  = make_float2(k0A * gaA,               k0B * gaB);
    float2 nk1   = make_float2(-k1A,                    -k1B);
    float2 k2m   = make_float2(1.0f - k2A,              1.0f - k2B);
    float2 k2ga  = make_float2(k2A * gaA,               k2B * gaB);
    float2 kd    = make_float2(kkbA * k2m.x,            kkbB * k2m.y);
    float2 kq1c  = make_float2(k1A * (1.0f - kbA) * gaA + kkbA * k2ga.x,
                               k1B * (1.0f - kbB) * gaB + kkbB * k2ga.y);

    // ================= main loop =================
    float S0A = 0.f, H0A = ngl.x, H1A = 0.f, H2A = 0.f;
    float S0B = 0.f, H0B = ngl.y, H1B = 0.f, H2B = 0.f;
    float4 fA[8], fB[8];
    float yA[8], yB[8];
    float rv, rw;

#define STEP(F, Y, K)                                                          \
    {                                                                          \
        float ps = (F).x, pl = (F).y, e = (F).z, tap = (F).w;                  \
        float plvi = pl * vi;                                                  \
        float plv1 = pl - plvi;                                                \
        float amA = tap * gm.x;                                                \
        float SmA = fminf(S0A, amA);                                           \
        S0A = (S0A - SmA) + ps;                                                \
        float G1A = fmaxf((H1A + SmA) + fmaf(e, nge.x, plvi), 0.f);            \
        float G0A = fmaxf((H0A + G1A) + plv1, 0.f);                            \
        H0A = fmaf(G0A, k0m.x, ngl.x);                                         \
        float yAv = G0A * k0ga.x;                                              \
        float m1A = fminf(G1A, gl.x);                                          \
        H1A = fminf(fmaf(m1A, nk1.x, G1A), gl.x);                              \
        yAv = fmaf(H2A, k2ga.x, yAv);                                          \
        yAv = fmaf(m1A, kq1c.x, yAv);                                          \
        float h2tA = H2A * k2m.x;                                              \
        H2A = fmaf(m1A, kd.x, h2tA);                                           \
        float amB = tap * gm.y;                                                \
        float SmB = fminf(S0B, amB);                                           \
        S0B = (S0B - SmB) + ps;                                                \
        float G1B = fmaxf((H1B + SmB) + fmaf(e, nge.y, plvi), 0.f);            \
        float G0B = fmaxf((H0B + G1B) + plv1, 0.f);                            \
        H0B = fmaf(G0B, k0m.y, ngl.y);                                         \
        float yBv = G0B * k0ga.y;                                              \
        float m1B = fminf(G1B, gl.y);                                          \
        H1B = fminf(fmaf(m1B, nk1.y, G1B), gl.y);                              \
        yBv = fmaf(H2B, k2ga.y, yBv);                                          \
        yBv = fmaf(m1B, kq1c.y, yBv);                                          \
        float h2tB = H2B * k2m.y;                                              \
        H2B = fmaf(m1B, kd.y, h2tB);                                           \
        (Y)[K] = yAv + yBv;                                                    \
    }

#define RSTG(Y, o, I0)                                                         \
    {                                                                          \
        float u0 = __shfl_xor_sync(0xffffffffu, (Y)[(I0) + 0], (o));           \
        float u1 = __shfl_xor_sync(0xffffffffu, (Y)[(I0) + 1], (o));           \
        float u2 = __shfl_xor_sync(0xffffffffu, (Y)[(I0) + 2], (o));           \
        float u3 = __shfl_xor_sync(0xffffffffu, (Y)[(I0) + 3], (o));           \
        (Y)[(I0) + 0] += u0; (Y)[(I0) + 1] += u1;                              \
        (Y)[(I0) + 2] += u2; (Y)[(I0) + 3] += u3;                              \
    }
#define RSEL8(Y)                                                               \
    {                                                                          \
        float a0 = (l3 & 1) ? (Y)[1] : (Y)[0];                                 \
        float a1 = (l3 & 1) ? (Y)[3] : (Y)[2];                                 \
        rv = (l3 & 2) ? a1 : a0;                                               \
        float b0 = (l3 & 1) ? (Y)[5] : (Y)[4];                                 \
        float b1 = (l3 & 1) ? (Y)[7] : (Y)[6];                                 \
        rw = (l3 & 2) ? b1 : b0;                                               \
    }
#define RSTG2(o)                                                               \
    {                                                                          \
        float u = __shfl_xor_sync(0xffffffffu, rv, (o));                       \
        float v = __shfl_xor_sync(0xffffffffu, rw, (o));                       \
        rv += u; rw += v;                                                      \
    }
#define RSTORE8(T)                                                             \
    if (lane < 4) {                                                            \
        out[(size_t)((T) + lane) * NS + s] = rv + qb;                          \
        out[(size_t)((T) + 4 + lane) * NS + s] = rw + qb;                      \
    }

    // one 8-step block: STEP into YCUR from FCUR, reduce YPREV, store TPREV
#define BLOCK8(FCUR, YCUR, YPREV, TPREV)                                       \
    STEP(FCUR[0], YCUR, 0)                                                     \
    RSTG(YPREV, 1, 0)                                                          \
    STEP(FCUR[1], YCUR, 1)                                                     \
    RSTG(YPREV, 1, 4)                                                          \
    STEP(FCUR[2], YCUR, 2)                                                     \
    RSTG(YPREV, 2, 0)                                                          \
    STEP(FCUR[3], YCUR, 3)                                                     \
    RSTG(YPREV, 2, 4)                                                          \
    STEP(FCUR[4], YCUR, 4)                                                     \
    RSEL8(YPREV)                                                               \
    STEP(FCUR[5], YCUR, 5)                                                     \
    RSTG2(4)                                                                   \
    STEP(FCUR[6], YCUR, 6)                                                     \
    RSTG2(8)                                                                   \
    STEP(FCUR[7], YCUR, 7)                                                     \
    RSTG2(16)                                                                  \
    RSTORE8(TPREV)

#define LOADBLK(DST)                                                           \
    {                                                                          \
        _Pragma("unroll")                                                      \
        for (int k = 0; k < 8; k++) DST[k] = pn[(size_t)k * NS];               \
        pn += (size_t)8 * NS;                                                  \
    }

    const float4* pn = g_flux + s;

    // preload fA = rows 0..7
    LOADBLK(fA)
    // block 0 (t=0): load fB (rows 8..15), STEP fA -> yA (no reduction yet)
    LOADBLK(fB)
    STEP(fA[0], yA, 0) STEP(fA[1], yA, 1) STEP(fA[2], yA, 2) STEP(fA[3], yA, 3)
    STEP(fA[4], yA, 4) STEP(fA[5], yA, 5) STEP(fA[6], yA, 6) STEP(fA[7], yA, 7)

    // 22 pairs: tb = 2pr+1 (uses fB, fills yB) and tb = 2pr+2 (uses fA, fills yA)
    for (int pr = 0; pr < 22; ++pr) {
        int t1 = pr * 16 + 8;
        LOADBLK(fA)                       // rows for tb = 2pr+2
        BLOCK8(fB, yB, yA, t1 - 8)
        LOADBLK(fB)                       // rows for tb = 2pr+3
        BLOCK8(fA, yA, yB, t1)
    }

    // drain block 44 reduction (t = 352..359); yA holds it
    RSTG(yA, 1, 0) RSTG(yA, 1, 4) RSTG(yA, 2, 0) RSTG(yA, 2, 4)
    RSEL8(yA) RSTG2(4) RSTG2(8) RSTG2(16)
    RSTORE8(352)

    // epilogue: t = 360..364 (fB holds rows 360..367)
#pragma unroll
    for (int k = 0; k < 5; k++) {
        STEP(fB[k], yA, 0)
        float r = yA[0];
#pragma unroll
        for (int o = 16; o; o >>= 1) r += __shfl_xor_sync(0xffffffffu, r, o);
        if (lane == 0) out[(size_t)(360 + k) * NS + s] = r + qb;
    }
#undef STEP
#undef RSTG
#undef RSEL8
#undef RSTG2
#undef RSTORE8
#undef BLOCK8
#undef LOADBLK
}

// ---------------- launch ------------------------------------------------------
extern "C" void kernel_launch(void* const* d_in, const int* in_sizes, int n_in,
                              void* d_out, int out_size) {
    const float* x  = (const float*)d_in[0];  // [NT, NS, 4]
    const float* xc = (const float*)d_in[1];  // [NS, NG]
    const float* W  = (const float*)d_in[2];  // [NW, NG]
    const float* b  = (const float*)d_in[3];  // [NW]
    float* out = (float*)d_out;               // [NT, NS]

    k_pre<<<GEMM_BLOCKS + PART_BLOCKS, 256>>>((const float4*)x, xc, W, b);
    k_scan<<<NS / 2, 64>>>(out, xc, W, b);   // fused params + scan
}